// round 13
// baseline (speedup 1.0000x reference)
#include <cuda_runtime.h>

// packed f32x2 FMA (PTX-only; ptxas never emits FFMA2 from C++)
#define FMA2(d, a, b, c) \
    asm("fma.rn.f32x2 %0, %1, %2, %3;" : "=l"(d) : "l"(a), "l"(b), "l"(c))

namespace cfg {
constexpr int H = 224, Wd = 224, C = 32, O = 32;
constexpr int TLW = 32, TLH = 16;     // output tile
constexpr int CCH = 8;                // channels per stage (4 stages; checkpoint after 2)
constexpr int TR  = 18;               // input rows per channel (16 + halo)
constexpr int S2  = 30;               // float2/row (cols 0..29 are all that's read)
constexpr int BUF2 = CCH * TR * S2;   // 4320 float2 per input buffer
constexpr int KW = C * 9;             // 288 taps per output channel
constexpr int TAPS_CONST = 216;       // taps (ch 0..23) whose dup weights fit constant
constexpr int TAPS_SMEM  = KW - TAPS_CONST;   // 72 taps (ch 24..31) -> smem
constexpr int W3_ELEMS = TAPS_SMEM * 32;      // 2304 float2 = 18,432 B
constexpr int SMEM_BYTES = 2 * BUF2 * 8 + W3_ELEMS * 8;  // 87,552 B -> 2 blocks/SM
}

// full duplicated table in global scratch: g_wdup[t*32+o] = (W[o][t], W[o][t])
__device__ float2 g_wdup[cfg::KW * 32];
// first 216 taps mirrored into the constant bank (55.3KB <= 64KB)
__constant__ float2 c_wd[cfg::TAPS_CONST * 32];

__global__ void weight_pack_kernel(const float* __restrict__ W)
{
    int i = blockIdx.x * 256 + threadIdx.x;
    if (i < cfg::KW * 32) {
        int t = i >> 5, o = i & 31;
        float w = W[o * cfg::KW + t];
        g_wdup[i] = make_float2(w, w);
    }
}

// 4B cp.async with zero-fill for OOB (src redirected to a safe address when !ok)
__device__ __forceinline__ void cpa4(unsigned dst, const float* src, bool ok)
{
    int sz = ok ? 4 : 0;
    asm volatile("cp.async.ca.shared.global [%0], [%1], 4, %2;"
                 :: "r"(dst), "l"(src), "r"(sz));
}
__device__ __forceinline__ void cpa16(unsigned dst, const void* src)
{
    asm volatile("cp.async.cg.shared.global [%0], [%1], 16;"
                 :: "r"(dst), "l"(src));
}

// one (c,dy) compute round against a weight table (constant or shared)
#define ROUND(WTBL, TAPBASE)                                                  \
    do {                                                                      \
        const ulonglong2* ir = reinterpret_cast<const ulonglong2*>(           \
            cur + (cl * TR + rr + dy) * S2 + 8 * xb);                         \
        ulonglong2 A = ir[0], B = ir[1], Cv = ir[2];                          \
        unsigned long long P[6] = {A.x, A.y, B.x, B.y, Cv.x, Cv.y};           \
        _Pragma("unroll")                                                     \
        for (int dx = 0; dx < 3; dx++) {                                      \
            const ulonglong2* wk = reinterpret_cast<const ulonglong2*>(       \
                (WTBL) + (((TAPBASE) + dx) * 32 + og * 4));                   \
            ulonglong2 wa = wk[0], wb = wk[1];                                \
            unsigned long long wp[4] = {wa.x, wa.y, wb.x, wb.y};              \
            _Pragma("unroll")                                                 \
            for (int o = 0; o < 4; o++) {                                     \
                _Pragma("unroll")                                             \
                for (int pp = 0; pp < 4; pp++)                                \
                    FMA2(acc[o * 4 + pp], P[pp + dx], wp[o], acc[o * 4 + pp]);\
            }                                                                 \
        }                                                                     \
    } while (0)

__global__ __launch_bounds__(512, 2)
void conv_early_kernel(const float* __restrict__ x, float* __restrict__ out)
{
    using namespace cfg;
    extern __shared__ float2 sm2[];      // [2 input buffers][stage-3 weight table]

    const int tid = threadIdx.x;
    const int wid = tid >> 5;            // warp 0..15 (staging role)
    const int l   = tid & 31;
    const int og  = tid >> 6;            // 0..7, warp-uniform: o = og*4 .. og*4+3
    const int pos = tid & 63;
    const int rr  = pos & 15;            // output row in tile
    const int xb  = (pos >> 4) & 3;      // x block of 8 px

    const int x0 = blockIdx.x * TLW;
    const int y0 = blockIdx.y * TLH;
    const int b  = blockIdx.z;
    const float* ximg = x + (size_t)b * C * H * Wd;
    const unsigned sbase = (unsigned)__cvta_generic_to_shared(sm2);
    float2* w3 = sm2 + 2 * BUF2;         // stage-3 dup weights (18.4KB)

    // staging role: warp w stages channel c = w/2, rows rbase = (w&1)*9 .. +8
    const int sc    = wid >> 1;
    const int rbase = (wid & 1) * 9;

    // input tile: in2[c][r][col] = (t[col], t[col+4]), t[j] = x[ch][y0-1+r][x0-1+j]
    auto issue_stage = [&](int stage) {
        unsigned bufb = sbase + (unsigned)((stage & 1) * (BUF2 * 8));
        const float* cp = ximg + (size_t)(stage * CCH + sc) * H * Wd;
        if (l < 30) {
            #pragma unroll 3
            for (int k = 0; k < 9; k++) {
                int r  = rbase + k;
                int gy = y0 - 1 + r;
                bool rok = (unsigned)gy < (unsigned)H;
                const float* srow = cp + (size_t)gy * Wd + (x0 - 1);
                unsigned drow = bufb + (unsigned)(((sc * TR + r) * S2) * 8);
                bool okx = rok && ((unsigned)(x0 - 1 + l) < (unsigned)Wd);
                cpa4(drow + l * 8,     okx ? srow + l : ximg, okx);
                bool oky = rok && ((unsigned)(x0 + 3 + l) < (unsigned)Wd);
                cpa4(drow + l * 8 + 4, oky ? srow + l + 4 : ximg, oky);
            }
        }
        asm volatile("cp.async.commit_group;" ::: "memory");
    };

    unsigned long long acc[16];          // acc[o*4+pp] = (px pp, px pp+4), o local
    #pragma unroll
    for (int i = 0; i < 16; i++) acc[i] = 0ull;
    unsigned mask = 0;                   // 32 early-terminate sign bits

    // one-time: stage-3 dup weights into smem (same commit group as stage 0)
    {
        unsigned wdst = sbase + (unsigned)(2 * BUF2 * 8);
        const char* wsrc = (const char*)(g_wdup + (size_t)TAPS_CONST * 32);
        #pragma unroll
        for (int i = tid; i < W3_ELEMS / 2; i += 512)
            cpa16(wdst + i * 16, wsrc + (size_t)i * 16);
    }
    issue_stage(0);

    #pragma unroll 1
    for (int stage = 0; stage < 4; stage++) {
        asm volatile("cp.async.wait_group 0;" ::: "memory");
        __syncthreads();                 // stage tile visible; prior readers done
        if (stage < 3) issue_stage(stage + 1);   // overlap next load with compute

        const float2* cur = sm2 + (stage & 1) * BUF2;

        if (stage < 3) {
            #pragma unroll 1
            for (int cl = 0; cl < CCH; cl++) {
                const int kb9 = (stage * CCH + cl) * 9;
                #pragma unroll
                for (int dy = 0; dy < 3; dy++)
                    ROUND(c_wd, kb9 + dy * 3);          // LDC.128 weight path
            }
        } else {
            #pragma unroll 1
            for (int cl = 0; cl < CCH; cl++) {
                const int kb9 = cl * 9;                 // local to smem table
                #pragma unroll
                for (int dy = 0; dy < 3; dy++)
                    ROUND(w3, kb9 + dy * 3);            // broadcast LDS path
            }
        }

        if (stage == 1) {
            // 16-channel checkpoint: sign of partial sum per output element
            #pragma unroll
            for (int i = 0; i < 16; i++) {
                float lo = __uint_as_float((unsigned)(acc[i] & 0xffffffffull));
                float hi = __uint_as_float((unsigned)(acc[i] >> 32));
                mask |= (lo < 0.f ? 1u : 0u) << (2 * i);
                mask |= (hi < 0.f ? 1u : 0u) << (2 * i + 1);
            }
        }
    }

    // ---- epilogue: out = maskbit ? 0 : relu(full) ----
    const int gy  = y0 + rr;
    const int gx0 = x0 + 8 * xb;
    #pragma unroll
    for (int o = 0; o < 4; o++) {
        float lo[4], hi[4];
        #pragma unroll
        for (int pp = 0; pp < 4; pp++) {
            unsigned long long a = acc[o * 4 + pp];
            float lv = __uint_as_float((unsigned)(a & 0xffffffffull));
            float hv = __uint_as_float((unsigned)(a >> 32));
            int bi = 2 * (o * 4 + pp);
            lo[pp] = ((mask >> bi)       & 1u) ? 0.f : fmaxf(lv, 0.f);
            hi[pp] = ((mask >> (bi + 1)) & 1u) ? 0.f : fmaxf(hv, 0.f);
        }
        float* p = out + (((size_t)b * O + og * 4 + o) * H + gy) * Wd + gx0;
        *reinterpret_cast<float4*>(p)     = make_float4(lo[0], lo[1], lo[2], lo[3]);
        *reinterpret_cast<float4*>(p + 4) = make_float4(hi[0], hi[1], hi[2], hi[3]);
    }
}

extern "C" void kernel_launch(void* const* d_in, const int* in_sizes, int n_in,
                              void* d_out, int out_size)
{
    using namespace cfg;
    const float* x = (const float*)d_in[0];   // [32][32][224][224] f32
    const float* W = (const float*)d_in[1];   // [32][32][3][3] f32
    float* out = (float*)d_out;

    // build full (w,w) dup table, mirror first 216 taps into constant bank
    weight_pack_kernel<<<(KW * 32 + 255) / 256, 256>>>(W);
    void* src = nullptr; void* dst = nullptr;
    cudaGetSymbolAddress(&src, g_wdup);
    cudaGetSymbolAddress(&dst, c_wd);
    cudaMemcpyAsync(dst, src, sizeof(float2) * TAPS_CONST * 32,
                    cudaMemcpyDeviceToDevice);

    cudaFuncSetAttribute(conv_early_kernel,
                         cudaFuncAttributeMaxDynamicSharedMemorySize, SMEM_BYTES);
    dim3 grid(Wd / TLW, H / TLH, 32);         // 7 x 14 x 32
    conv_early_kernel<<<grid, 512, SMEM_BYTES>>>(x, out);
}

// round 14
// speedup vs baseline: 1.1369x; 1.1369x over previous
#include <cuda_runtime.h>

// packed f32x2 FMA + pack (PTX-only; ptxas never emits FFMA2 from C++)
#define FMA2(d, a, b, c) \
    asm("fma.rn.f32x2 %0, %1, %2, %3;" : "=l"(d) : "l"(a), "l"(b), "l"(c))
#define PACK2(d, lo, hi) \
    asm("mov.b64 %0, {%1, %2};" : "=l"(d) : "f"(lo), "f"(hi))

namespace cfg {
constexpr int H = 224, Wd = 224, C = 32, O = 32;
constexpr int TLW = 32, TLH = 16;     // output tile
constexpr int CCH = 8;                // channels per stage (4 stages; checkpoint after 2)
constexpr int TR  = 18;               // input rows per channel (16 + halo)
constexpr int S2  = 30;               // float2/row (cols 0..29 are all that's read)
constexpr int BUF2 = CCH * TR * S2;   // 4320 float2 per input buffer
constexpr int SMEM_BYTES = 2 * BUF2 * 8;  // 69,120 B double-buffered -> 2 blocks/SM
constexpr int KW = C * 9;             // 288 taps per output channel
}

// scalar weights transposed: c_ws[k*32 + o] = W[o][k], k = c*9+dy*3+dx  (36.9KB)
__device__ float g_wtmp[cfg::KW * 32];
__constant__ float c_ws[cfg::KW * 32];

__global__ void weight_pack_kernel(const float* __restrict__ W)
{
    int i = blockIdx.x * 256 + threadIdx.x;
    if (i < cfg::KW * 32) {
        int k = i >> 5, o = i & 31;
        g_wtmp[i] = W[o * cfg::KW + k];
    }
}

// 4B cp.async with zero-fill for OOB (src redirected to a safe address when !ok)
__device__ __forceinline__ void cpa4(unsigned dst, const float* src, bool ok)
{
    int sz = ok ? 4 : 0;
    asm volatile("cp.async.ca.shared.global [%0], [%1], 4, %2;"
                 :: "r"(dst), "l"(src), "r"(sz));
}

// 4 FMA2s against one scalar weight component (wp built fresh, 2-reg lifetime)
#define OTAP(WF, OIDX, DX)                                              \
    do {                                                                \
        unsigned long long wp;                                          \
        PACK2(wp, (WF), (WF));                                          \
        FMA2(acc[(OIDX)*4 + 0], P[0 + (DX)], wp, acc[(OIDX)*4 + 0]);    \
        FMA2(acc[(OIDX)*4 + 1], P[1 + (DX)], wp, acc[(OIDX)*4 + 1]);    \
        FMA2(acc[(OIDX)*4 + 2], P[2 + (DX)], wp, acc[(OIDX)*4 + 2]);    \
        FMA2(acc[(OIDX)*4 + 3], P[3 + (DX)], wp, acc[(OIDX)*4 + 3]);    \
    } while (0)

#define DXBLK(WV, DX)                                                   \
    do {                                                                \
        OTAP((WV).x, 0, DX); OTAP((WV).y, 1, DX);                       \
        OTAP((WV).z, 2, DX); OTAP((WV).w, 3, DX);                       \
    } while (0)

__global__ __launch_bounds__(512, 2)
void conv_early_kernel(const float* __restrict__ x, float* __restrict__ out)
{
    using namespace cfg;
    extern __shared__ float2 sbuf[];     // two BUF2-sized pixel-pair buffers

    const int tid = threadIdx.x;
    const int wid = tid >> 5;            // warp 0..15 (staging role)
    const int l   = tid & 31;
    const int og  = tid >> 6;            // 0..7, warp-uniform: o = og*4 .. og*4+3
    const int pos = tid & 63;
    const int rr  = pos & 15;            // output row in tile
    const int xb  = (pos >> 4) & 3;      // x block of 8 px

    const int x0 = blockIdx.x * TLW;
    const int y0 = blockIdx.y * TLH;
    const int b  = blockIdx.z;
    const float* ximg = x + (size_t)b * C * H * Wd;
    const unsigned sbase = (unsigned)__cvta_generic_to_shared(sbuf);

    // staging role: warp w stages channel c = w/2, rows rbase = (w&1)*9 .. +8
    const int sc    = wid >> 1;
    const int rbase = (wid & 1) * 9;

    // input tile: in2[c][r][col] = (t[col], t[col+4]), t[j] = x[ch][y0-1+r][x0-1+j]
    auto issue_stage = [&](int stage) {
        unsigned bufb = sbase + (unsigned)((stage & 1) * (BUF2 * 8));
        const float* cp = ximg + (size_t)(stage * CCH + sc) * H * Wd;
        if (l < 30) {
            #pragma unroll 3
            for (int k = 0; k < 9; k++) {
                int r  = rbase + k;
                int gy = y0 - 1 + r;
                bool rok = (unsigned)gy < (unsigned)H;
                const float* srow = cp + (size_t)gy * Wd + (x0 - 1);
                unsigned drow = bufb + (unsigned)(((sc * TR + r) * S2) * 8);
                bool okx = rok && ((unsigned)(x0 - 1 + l) < (unsigned)Wd);
                cpa4(drow + l * 8,     okx ? srow + l : ximg, okx);
                bool oky = rok && ((unsigned)(x0 + 3 + l) < (unsigned)Wd);
                cpa4(drow + l * 8 + 4, oky ? srow + l + 4 : ximg, oky);
            }
        }
        asm volatile("cp.async.commit_group;" ::: "memory");
    };

    unsigned long long acc[16];          // acc[o*4+pp] = (px pp, px pp+4), o local
    #pragma unroll
    for (int i = 0; i < 16; i++) acc[i] = 0ull;
    unsigned mask = 0;                   // 32 early-terminate sign bits

    const float4* cwf = reinterpret_cast<const float4*>(c_ws);

    issue_stage(0);

    #pragma unroll 1
    for (int stage = 0; stage < 4; stage++) {
        asm volatile("cp.async.wait_group 0;" ::: "memory");
        __syncthreads();                 // stage tile visible; prior readers done
        if (stage < 3) issue_stage(stage + 1);   // overlap next load with compute

        const float2* cur = sbuf + (stage & 1) * BUF2;

        #pragma unroll 1
        for (int cl = 0; cl < CCH; cl++) {
            const int kb9 = (stage * CCH + cl) * 9;
            #pragma unroll
            for (int dy = 0; dy < 3; dy++) {
                // --- all long-latency loads of this round, front-loaded ---
                const int kk = (kb9 + dy * 3) * 8 + og;
                float4 w0 = cwf[kk];                 // LDC.128 x3, issued early
                float4 w1 = cwf[kk + 8];
                float4 w2 = cwf[kk + 16];
                const ulonglong2* ir = reinterpret_cast<const ulonglong2*>(
                    cur + (cl * TR + rr + dy) * S2 + 8 * xb);
                ulonglong2 A = ir[0], B = ir[1], Cv = ir[2];  // LDS.128 x3
                unsigned long long P[6] = {A.x, A.y, B.x, B.y, Cv.x, Cv.y};
                // --- FMA burst; wp built one-at-a-time (2-reg lifetime) ---
                DXBLK(w0, 0);
                DXBLK(w1, 1);
                DXBLK(w2, 2);
            }
        }

        if (stage == 1) {
            // 16-channel checkpoint: sign of partial sum per output element
            #pragma unroll
            for (int i = 0; i < 16; i++) {
                float lo = __uint_as_float((unsigned)(acc[i] & 0xffffffffull));
                float hi = __uint_as_float((unsigned)(acc[i] >> 32));
                mask |= (lo < 0.f ? 1u : 0u) << (2 * i);
                mask |= (hi < 0.f ? 1u : 0u) << (2 * i + 1);
            }
        }
    }

    // ---- epilogue: out = maskbit ? 0 : relu(full) ----
    const int gy  = y0 + rr;
    const int gx0 = x0 + 8 * xb;
    #pragma unroll
    for (int o = 0; o < 4; o++) {
        float lo[4], hi[4];
        #pragma unroll
        for (int pp = 0; pp < 4; pp++) {
            unsigned long long a = acc[o * 4 + pp];
            float lv = __uint_as_float((unsigned)(a & 0xffffffffull));
            float hv = __uint_as_float((unsigned)(a >> 32));
            int bi = 2 * (o * 4 + pp);
            lo[pp] = ((mask >> bi)       & 1u) ? 0.f : fmaxf(lv, 0.f);
            hi[pp] = ((mask >> (bi + 1)) & 1u) ? 0.f : fmaxf(hv, 0.f);
        }
        float* p = out + (((size_t)b * O + og * 4 + o) * H + gy) * Wd + gx0;
        *reinterpret_cast<float4*>(p)     = make_float4(lo[0], lo[1], lo[2], lo[3]);
        *reinterpret_cast<float4*>(p + 4) = make_float4(hi[0], hi[1], hi[2], hi[3]);
    }
}

extern "C" void kernel_launch(void* const* d_in, const int* in_sizes, int n_in,
                              void* d_out, int out_size)
{
    using namespace cfg;
    const float* x = (const float*)d_in[0];   // [32][32][224][224] f32
    const float* W = (const float*)d_in[1];   // [32][32][3][3] f32
    float* out = (float*)d_out;

    // transpose weights to [k][o] scalars, stage into constant bank
    weight_pack_kernel<<<(KW * 32 + 255) / 256, 256>>>(W);
    void* src = nullptr; void* dst = nullptr;
    cudaGetSymbolAddress(&src, g_wtmp);
    cudaGetSymbolAddress(&dst, c_ws);
    cudaMemcpyAsync(dst, src, sizeof(float) * KW * 32, cudaMemcpyDeviceToDevice);

    cudaFuncSetAttribute(conv_early_kernel,
                         cudaFuncAttributeMaxDynamicSharedMemorySize, SMEM_BYTES);
    dim3 grid(Wd / TLW, H / TLH, 32);         // 7 x 14 x 32
    conv_early_kernel<<<grid, 512, SMEM_BYTES>>>(x, out);
}